// round 2
// baseline (speedup 1.0000x reference)
#include <cuda_runtime.h>

#define NNODES_MAX 40000
#define D 128
#define D4 32

// ---------------- device scratch (no allocation allowed) ----------------
__device__ __align__(16) float g_agg[NNODES_MAX * D];   // (1+eps)*x + segment_sum(relu(x[src]))
__device__ __align__(16) float g_h1 [NNODES_MAX * D];   // h @ W1.T + b1
__device__ __align__(16) float g_sum[D];
__device__ __align__(16) float g_sq [D];
__device__ __align__(16) float g_scale[D];              // BN folded scale
__device__ __align__(16) float g_shift[D];              // BN folded shift

// ---------------- tiny kernels ----------------
__global__ void k_zero_stats() {
    int t = threadIdx.x;
    if (t < D) { g_sum[t] = 0.f; g_sq[t] = 0.f; }
}

__global__ void k_init_agg(const float* __restrict__ x, const float* __restrict__ eps, int n4) {
    int i = blockIdx.x * blockDim.x + threadIdx.x;
    if (i >= n4) return;
    float s = 1.0f + eps[0];
    float4 v = ((const float4*)x)[i];
    v.x *= s; v.y *= s; v.z *= s; v.w *= s;
    ((float4*)g_agg)[i] = v;
}

// ---------------- edge scatter: one warp per edge ----------------
__device__ __forceinline__ void red_add_v4(float* addr, float4 v) {
    asm volatile("red.global.add.v4.f32 [%0], {%1, %2, %3, %4};"
                 :: "l"(addr), "f"(v.x), "f"(v.y), "f"(v.z), "f"(v.w) : "memory");
}

__global__ void k_scatter(const float* __restrict__ x,
                          const int* __restrict__ src,
                          const int* __restrict__ dst, int E, int N) {
    int lane = threadIdx.x & 31;
    int warp = (blockIdx.x * blockDim.x + threadIdx.x) >> 5;
    int nwarps = (gridDim.x * blockDim.x) >> 5;
    for (int e = warp; e < E; e += nwarps) {
        int s = src[e];
        int d = dst[e];
        if ((unsigned)s >= (unsigned)N || (unsigned)d >= (unsigned)N) continue;
        float4 v = ((const float4*)(x + (long long)s * D))[lane];
        v.x = fmaxf(v.x, 0.f); v.y = fmaxf(v.y, 0.f);
        v.z = fmaxf(v.z, 0.f); v.w = fmaxf(v.w, 0.f);
        red_add_v4(g_agg + (long long)d * D + (lane << 2), v);
    }
}

// ---------------- column stats over g_h1 (for BatchNorm) ----------------
__global__ void k_colstats(int nrows) {
    __shared__ float ssum[256], ssq[256];
    int col  = threadIdx.x & 127;
    int half = threadIdx.x >> 7;
    int row0 = blockIdx.x * 128;
    int rend = row0 + 128; if (rend > nrows) rend = nrows;
    float s = 0.f, q = 0.f;
    for (int r = row0 + half; r < rend; r += 2) {
        float v = g_h1[r * D + col];
        s += v; q += v * v;
    }
    ssum[threadIdx.x] = s; ssq[threadIdx.x] = q;
    __syncthreads();
    if (half == 0) {
        s = ssum[col] + ssum[col + 128];
        q = ssq [col] + ssq [col + 128];
        atomicAdd(&g_sum[col], s);
        atomicAdd(&g_sq [col], q);
    }
}

__global__ void k_bnfinal(const float* __restrict__ gamma,
                          const float* __restrict__ beta, int nrows) {
    int j = threadIdx.x;
    if (j >= D) return;
    float invN = 1.0f / (float)nrows;
    float mu   = g_sum[j] * invN;
    float var  = g_sq[j] * invN - mu * mu;
    float inv  = rsqrtf(var + 1e-5f);
    float sc   = inv * gamma[j];
    g_scale[j] = sc;
    g_shift[j] = beta[j] - mu * sc;
}

// ---------------- fp32 GEMM: C[i,j] = sum_k A[i,k] * W[j,k] + bias[j] ----------------
// MODE 0: A = g_agg, C = g_h1 (plain)
// MODE 1: A = BNReLU(g_h1), C = out (BN scale/shift + relu applied on A-tile load)
template <int MODE>
__global__ void __launch_bounds__(256) k_gemm(const float* __restrict__ W,
                                              const float* __restrict__ bias,
                                              float* __restrict__ out, int nrows) {
    __shared__ float sA[16][D + 4];   // [k][row]
    __shared__ float sW[16][D + 4];   // [k][col]
    const float* __restrict__ A = (MODE == 0) ? g_agg : g_h1;
    float* __restrict__ C       = (MODE == 0) ? g_h1  : out;

    int tid = threadIdx.x;
    int tx = tid & 15, ty = tid >> 4;
    int rowbase = blockIdx.x * 128;

    float acc[8][8];
#pragma unroll
    for (int a = 0; a < 8; a++)
#pragma unroll
        for (int b = 0; b < 8; b++) acc[a][b] = 0.f;

    for (int t = 0; t < 8; ++t) {
        // load+transpose A tile: rows [rowbase,+128), k in [t*16, t*16+16)
#pragma unroll
        for (int i = tid; i < 128 * 4; i += 256) {
            int row = i >> 2;
            int kq  = i & 3;
            int grow = rowbase + row;
            float4 v = make_float4(0.f, 0.f, 0.f, 0.f);
            if (grow < nrows) v = ((const float4*)A)[grow * D4 + t * 4 + kq];
            if (MODE == 1) {
                int k = t * 16 + kq * 4;
                float4 sc = *(const float4*)&g_scale[k];
                float4 sh = *(const float4*)&g_shift[k];
                v.x = fmaxf(fmaf(v.x, sc.x, sh.x), 0.f);
                v.y = fmaxf(fmaf(v.y, sc.y, sh.y), 0.f);
                v.z = fmaxf(fmaf(v.z, sc.z, sh.z), 0.f);
                v.w = fmaxf(fmaf(v.w, sc.w, sh.w), 0.f);
            }
            int k = kq * 4;
            sA[k + 0][row] = v.x; sA[k + 1][row] = v.y;
            sA[k + 2][row] = v.z; sA[k + 3][row] = v.w;
        }
        // load+transpose W tile: all 128 j, k in [t*16, t*16+16)
#pragma unroll
        for (int i = tid; i < 128 * 4; i += 256) {
            int j  = i >> 2;
            int kq = i & 3;
            float4 v = ((const float4*)W)[j * D4 + t * 4 + kq];
            int k = kq * 4;
            sW[k + 0][j] = v.x; sW[k + 1][j] = v.y;
            sW[k + 2][j] = v.z; sW[k + 3][j] = v.w;
        }
        __syncthreads();
#pragma unroll
        for (int k = 0; k < 16; ++k) {
            float a[8], b[8];
#pragma unroll
            for (int ii = 0; ii < 8; ii++) a[ii] = sA[k][ty + ii * 16];
#pragma unroll
            for (int jj = 0; jj < 8; jj++) b[jj] = sW[k][tx + jj * 16];
#pragma unroll
            for (int ii = 0; ii < 8; ii++)
#pragma unroll
                for (int jj = 0; jj < 8; jj++)
                    acc[ii][jj] = fmaf(a[ii], b[jj], acc[ii][jj]);
        }
        __syncthreads();
    }

    float bj[8];
#pragma unroll
    for (int jj = 0; jj < 8; jj++) bj[jj] = bias[tx + jj * 16];
#pragma unroll
    for (int ii = 0; ii < 8; ii++) {
        int r = rowbase + ty + ii * 16;
        if (r < nrows) {
#pragma unroll
            for (int jj = 0; jj < 8; jj++)
                C[r * D + tx + jj * 16] = acc[ii][jj] + bj[jj];
        }
    }
}

// ---------------- launch ----------------
extern "C" void kernel_launch(void* const* d_in, const int* in_sizes, int n_in,
                              void* d_out, int out_size) {
    const float* x     = (const float*)d_in[0];
    const int*   src   = (const int*)d_in[1];
    const int*   dst   = (const int*)d_in[2];
    const float* W1    = (const float*)d_in[3];
    const float* b1    = (const float*)d_in[4];
    const float* gamma = (const float*)d_in[5];
    const float* beta  = (const float*)d_in[6];
    const float* W2    = (const float*)d_in[7];
    const float* b2    = (const float*)d_in[8];
    const float* eps   = (const float*)d_in[9];
    float* out = (float*)d_out;

    int N = in_sizes[0] / D;     // 40000
    int E = in_sizes[1];         // 640000
    int n4 = N * D4;

    k_zero_stats<<<1, 128>>>();
    k_init_agg<<<(n4 + 255) / 256, 256>>>(x, eps, n4);
    k_scatter<<<2048, 256>>>(x, src, dst, E, N);

    int gb = (N + 127) / 128;
    k_gemm<0><<<gb, 256>>>(W1, b1, nullptr, N);
    k_colstats<<<gb, 256>>>(N);
    k_bnfinal<<<1, 128>>>(gamma, beta, N);
    k_gemm<1><<<gb, 256>>>(W2, b2, out, N);
}

// round 4
// speedup vs baseline: 1.0220x; 1.0220x over previous
#include <cuda_runtime.h>
#include <cstdint>

#define NNODES_MAX 40000
#define D 128
#define D4 32

// ---------------- device scratch (no allocation allowed) ----------------
__device__ __align__(16) float g_agg[NNODES_MAX * D];
__device__ __align__(16) float g_h1 [NNODES_MAX * D];
__device__ __align__(16) float g_sum[D];
__device__ __align__(16) float g_sq [D];
__device__ __align__(16) float g_scale[D];
__device__ __align__(16) float g_shift[D];

__device__ __forceinline__ uint32_t f2tf32(float x) {
    uint32_t r; asm("cvt.rna.tf32.f32 %0, %1;" : "=r"(r) : "f"(x)); return r;
}

// ---------------- tiny kernels ----------------
__global__ void k_zero_stats() {
    int t = threadIdx.x;
    if (t < D) { g_sum[t] = 0.f; g_sq[t] = 0.f; }
}

__global__ void k_init_agg(const float* __restrict__ x, const float* __restrict__ eps, int n4) {
    int i = blockIdx.x * blockDim.x + threadIdx.x;
    if (i >= n4) return;
    float s = 1.0f + eps[0];
    float4 v = ((const float4*)x)[i];
    v.x *= s; v.y *= s; v.z *= s; v.w *= s;
    ((float4*)g_agg)[i] = v;
}

// ---------------- edge scatter: one warp per edge ----------------
__device__ __forceinline__ void red_add_v4(float* addr, float4 v) {
    asm volatile("red.global.add.v4.f32 [%0], {%1, %2, %3, %4};"
                 :: "l"(addr), "f"(v.x), "f"(v.y), "f"(v.z), "f"(v.w) : "memory");
}

__global__ void k_scatter(const float* __restrict__ x,
                          const int* __restrict__ src,
                          const int* __restrict__ dst, int E, int N) {
    int lane = threadIdx.x & 31;
    int warp = (blockIdx.x * blockDim.x + threadIdx.x) >> 5;
    int nwarps = (gridDim.x * blockDim.x) >> 5;
    for (int e = warp; e < E; e += nwarps) {
        int s = src[e];
        int d = dst[e];
        if ((unsigned)s >= (unsigned)N || (unsigned)d >= (unsigned)N) continue;
        float4 v = ((const float4*)(x + (long long)s * D))[lane];
        v.x = fmaxf(v.x, 0.f); v.y = fmaxf(v.y, 0.f);
        v.z = fmaxf(v.z, 0.f); v.w = fmaxf(v.w, 0.f);
        red_add_v4(g_agg + (long long)d * D + (lane << 2), v);
    }
}

__global__ void k_bnfinal(const float* __restrict__ gamma,
                          const float* __restrict__ beta, int nrows) {
    int j = threadIdx.x;
    if (j >= D) return;
    float invN = 1.0f / (float)nrows;
    float mu   = g_sum[j] * invN;
    float var  = g_sq[j] * invN - mu * mu;
    float inv  = rsqrtf(var + 1e-5f);
    float sc   = inv * gamma[j];
    g_scale[j] = sc;
    g_shift[j] = beta[j] - mu * sc;
}

// ---------------- tf32 mma.sync GEMM: C[i,j] = sum_k A[i,k]*W[j,k] + bias[j] ----------------
// MODE 0: A = g_agg -> C = g_h1, fused BN column-stat accumulation into g_sum/g_sq.
// MODE 1: A = BNReLU(g_h1) -> C = out.
// Block tile 128x128, K chunked 4x32. 8 warps as 2(m) x 4(n); warp tile 64x32.
__device__ __forceinline__ void mma_tf32(float* c, const uint32_t* a, const uint32_t* b) {
    asm volatile("mma.sync.aligned.m16n8k8.row.col.f32.tf32.tf32.f32 "
                 "{%0,%1,%2,%3}, {%4,%5,%6,%7}, {%8,%9}, {%0,%1,%2,%3};"
                 : "+f"(c[0]), "+f"(c[1]), "+f"(c[2]), "+f"(c[3])
                 : "r"(a[0]), "r"(a[1]), "r"(a[2]), "r"(a[3]), "r"(b[0]), "r"(b[1]));
}

template <int MODE>
__global__ void __launch_bounds__(256) k_gemm_mma(const float* __restrict__ Wm,
                                                  const float* __restrict__ bias,
                                                  float* __restrict__ outp, int nrows) {
    __shared__ float sA[128][36];   // [row][k] chunk, stride 36 => conflict-free frag loads
    __shared__ float sB[128][36];   // [n]  [k] chunk

    const float* __restrict__ A = (MODE == 0) ? g_agg : g_h1;
    float* __restrict__ Cp      = (MODE == 0) ? g_h1  : outp;

    int tid  = threadIdx.x;
    int wid  = tid >> 5, lane = tid & 31;
    int g    = lane >> 2, t4 = lane & 3;
    int wm   = (wid >> 2) * 64;       // warp m-offset: 0 / 64
    int wn   = (wid & 3) * 32;        // warp n-offset: 0/32/64/96
    int rowbase = blockIdx.x * 128;

    float acc[4][4][4];
#pragma unroll
    for (int mi = 0; mi < 4; mi++)
#pragma unroll
        for (int nj = 0; nj < 4; nj++)
#pragma unroll
            for (int q = 0; q < 4; q++) acc[mi][nj][q] = 0.f;

    for (int kc = 0; kc < 4; ++kc) {
        // ---- load A chunk (128 rows x 32 k) and B chunk (128 n x 32 k), tf32-rounded ----
#pragma unroll
        for (int it = 0; it < 4; ++it) {
            int i  = tid + it * 256;          // 0..1023 float4 slots for A
            int r  = i >> 3;
            int c4 = i & 7;
            int grow = rowbase + r;
            float4 v = make_float4(0.f, 0.f, 0.f, 0.f);
            if (grow < nrows) v = ((const float4*)A)[(size_t)grow * D4 + kc * 8 + c4];
            if (MODE == 1) {
                int k0 = kc * 32 + c4 * 4;
                float4 sc = *(const float4*)&g_scale[k0];
                float4 sh = *(const float4*)&g_shift[k0];
                v.x = fmaxf(fmaf(v.x, sc.x, sh.x), 0.f);
                v.y = fmaxf(fmaf(v.y, sc.y, sh.y), 0.f);
                v.z = fmaxf(fmaf(v.z, sc.z, sh.z), 0.f);
                v.w = fmaxf(fmaf(v.w, sc.w, sh.w), 0.f);
            }
            float* p = &sA[r][c4 * 4];
            p[0] = __uint_as_float(f2tf32(v.x));
            p[1] = __uint_as_float(f2tf32(v.y));
            p[2] = __uint_as_float(f2tf32(v.z));
            p[3] = __uint_as_float(f2tf32(v.w));
        }
#pragma unroll
        for (int it = 0; it < 4; ++it) {
            int i  = tid + it * 256;
            int r  = i >> 3;
            int c4 = i & 7;
            float4 v = ((const float4*)Wm)[(size_t)r * D4 + kc * 8 + c4];
            float* p = &sB[r][c4 * 4];
            p[0] = __uint_as_float(f2tf32(v.x));
            p[1] = __uint_as_float(f2tf32(v.y));
            p[2] = __uint_as_float(f2tf32(v.z));
            p[3] = __uint_as_float(f2tf32(v.w));
        }
        __syncthreads();

#pragma unroll
        for (int ks = 0; ks < 4; ++ks) {
            int k0 = ks * 8;
            uint32_t af[4][4];
#pragma unroll
            for (int mi = 0; mi < 4; mi++) {
                int r = wm + mi * 16 + g;
                af[mi][0] = __float_as_uint(sA[r    ][k0 + t4    ]);
                af[mi][1] = __float_as_uint(sA[r + 8][k0 + t4    ]);
                af[mi][2] = __float_as_uint(sA[r    ][k0 + t4 + 4]);
                af[mi][3] = __float_as_uint(sA[r + 8][k0 + t4 + 4]);
            }
            uint32_t bf[4][2];
#pragma unroll
            for (int nj = 0; nj < 4; nj++) {
                int c = wn + nj * 8 + g;
                bf[nj][0] = __float_as_uint(sB[c][k0 + t4    ]);
                bf[nj][1] = __float_as_uint(sB[c][k0 + t4 + 4]);
            }
#pragma unroll
            for (int mi = 0; mi < 4; mi++)
#pragma unroll
                for (int nj = 0; nj < 4; nj++)
                    mma_tf32(acc[mi][nj], af[mi], bf[nj]);
        }
        __syncthreads();
    }

    // ---- epilogue: bias add, store, (MODE 0) fused BN column stats ----
    float bj0[4], bj1[4];
#pragma unroll
    for (int nj = 0; nj < 4; nj++) {
        int c = wn + nj * 8 + 2 * t4;
        bj0[nj] = bias[c];
        bj1[nj] = bias[c + 1];
    }

    float s0[4], s1[4], q0[4], q1[4];
#pragma unroll
    for (int nj = 0; nj < 4; nj++) { s0[nj] = s1[nj] = q0[nj] = q1[nj] = 0.f; }

#pragma unroll
    for (int mi = 0; mi < 4; mi++) {
        int r0 = rowbase + wm + mi * 16 + g;
        int r1 = r0 + 8;
#pragma unroll
        for (int nj = 0; nj < 4; nj++) {
            int c = wn + nj * 8 + 2 * t4;
            float v00 = acc[mi][nj][0] + bj0[nj];
            float v01 = acc[mi][nj][1] + bj1[nj];
            float v10 = acc[mi][nj][2] + bj0[nj];
            float v11 = acc[mi][nj][3] + bj1[nj];
            if (r0 < nrows) {
                *(float2*)&Cp[(size_t)r0 * D + c] = make_float2(v00, v01);
                if (MODE == 0) {
                    s0[nj] += v00; s1[nj] += v01;
                    q0[nj] = fmaf(v00, v00, q0[nj]); q1[nj] = fmaf(v01, v01, q1[nj]);
                }
            }
            if (r1 < nrows) {
                *(float2*)&Cp[(size_t)r1 * D + c] = make_float2(v10, v11);
                if (MODE == 0) {
                    s0[nj] += v10; s1[nj] += v11;
                    q0[nj] = fmaf(v10, v10, q0[nj]); q1[nj] = fmaf(v11, v11, q1[nj]);
                }
            }
        }
    }

    if (MODE == 0) {
        // reduce over the 8 row-groups (lane bits 2..4), lanes 0..3 hold col-pair totals
#pragma unroll
        for (int nj = 0; nj < 4; nj++) {
#pragma unroll
            for (int m = 4; m <= 16; m <<= 1) {
                s0[nj] += __shfl_xor_sync(0xFFFFFFFFu, s0[nj], m);
                s1[nj] += __shfl_xor_sync(0xFFFFFFFFu, s1[nj], m);
                q0[nj] += __shfl_xor_sync(0xFFFFFFFFu, q0[nj], m);
                q1[nj] += __shfl_xor_sync(0xFFFFFFFFu, q1[nj], m);
            }
        }
        if (lane < 4) {
#pragma unroll
            for (int nj = 0; nj < 4; nj++) {
                int c = wn + nj * 8 + 2 * t4;
                atomicAdd(&g_sum[c],     s0[nj]);
                atomicAdd(&g_sum[c + 1], s1[nj]);
                atomicAdd(&g_sq [c],     q0[nj]);
                atomicAdd(&g_sq [c + 1], q1[nj]);
            }
        }
    }
}

// ---------------- launch ----------------
extern "C" void kernel_launch(void* const* d_in, const int* in_sizes, int n_in,
                              void* d_out, int out_size) {
    const float* x     = (const float*)d_in[0];
    const int*   src   = (const int*)d_in[1];
    const int*   dst   = (const int*)d_in[2];
    const float* W1    = (const float*)d_in[3];
    const float* b1    = (const float*)d_in[4];
    const float* gamma = (const float*)d_in[5];
    const float* beta  = (const float*)d_in[6];
    const float* W2    = (const float*)d_in[7];
    const float* b2    = (const float*)d_in[8];
    const float* eps   = (const float*)d_in[9];
    float* out = (float*)d_out;

    int N = in_sizes[0] / D;     // 40000
    int E = in_sizes[1];         // 640000
    int n4 = N * D4;

    k_zero_stats<<<1, 128>>>();
    k_init_agg<<<(n4 + 255) / 256, 256>>>(x, eps, n4);
    k_scatter<<<2048, 256>>>(x, src, dst, E, N);

    int gb = (N + 127) / 128;
    k_gemm_mma<0><<<gb, 256>>>(W1, b1, nullptr, N);   // + fused BN stats
    k_bnfinal<<<1, 128>>>(gamma, beta, N);
    k_gemm_mma<1><<<gb, 256>>>(W2, b2, out, N);
}

// round 5
// speedup vs baseline: 1.4880x; 1.4561x over previous
#include <cuda_runtime.h>
#include <cstdint>

#define NNODES_MAX 40000
#define D 128
#define D4 32

// ---------------- device scratch (no allocation allowed) ----------------
__device__ __align__(16) float g_agg[NNODES_MAX * D];
__device__ __align__(16) float g_h1 [NNODES_MAX * D];
__device__ __align__(16) float g_sum[D];
__device__ __align__(16) float g_sq [D];
__device__ __align__(16) float g_scale[D];
__device__ __align__(16) float g_shift[D];

__device__ __forceinline__ uint32_t f2tf32(float x) {
    uint32_t r; asm("cvt.rna.tf32.f32 %0, %1;" : "=r"(r) : "f"(x)); return r;
}

// ---------------- init: residual scale + zero BN stats (fused) ----------------
__global__ void k_init_agg(const float* __restrict__ x, const float* __restrict__ eps, int n4) {
    int i = blockIdx.x * blockDim.x + threadIdx.x;
    if (blockIdx.x == 0 && threadIdx.x < D) { g_sum[threadIdx.x] = 0.f; g_sq[threadIdx.x] = 0.f; }
    if (i >= n4) return;
    float s = 1.0f + eps[0];
    float4 v = ((const float4*)x)[i];
    v.x *= s; v.y *= s; v.z *= s; v.w *= s;
    ((float4*)g_agg)[i] = v;
}

// ---------------- edge scatter: one warp per edge ----------------
__device__ __forceinline__ void red_add_v4(float* addr, float4 v) {
    asm volatile("red.global.add.v4.f32 [%0], {%1, %2, %3, %4};"
                 :: "l"(addr), "f"(v.x), "f"(v.y), "f"(v.z), "f"(v.w) : "memory");
}

__global__ void k_scatter(const float* __restrict__ x,
                          const int* __restrict__ src,
                          const int* __restrict__ dst, int E, int N) {
    int lane = threadIdx.x & 31;
    int warp = (blockIdx.x * blockDim.x + threadIdx.x) >> 5;
    int nwarps = (gridDim.x * blockDim.x) >> 5;
    for (int e = warp; e < E; e += nwarps) {
        int s = src[e];
        int d = dst[e];
        if ((unsigned)s >= (unsigned)N || (unsigned)d >= (unsigned)N) continue;
        float4 v = ((const float4*)(x + (long long)s * D))[lane];
        v.x = fmaxf(v.x, 0.f); v.y = fmaxf(v.y, 0.f);
        v.z = fmaxf(v.z, 0.f); v.w = fmaxf(v.w, 0.f);
        red_add_v4(g_agg + (long long)d * D + (lane << 2), v);
    }
}

__global__ void k_bnfinal(const float* __restrict__ gamma,
                          const float* __restrict__ beta, int nrows) {
    int j = threadIdx.x;
    if (j >= D) return;
    float invN = 1.0f / (float)nrows;
    float mu   = g_sum[j] * invN;
    float var  = g_sq[j] * invN - mu * mu;
    float inv  = rsqrtf(var + 1e-5f);
    float sc   = inv * gamma[j];
    g_scale[j] = sc;
    g_shift[j] = beta[j] - mu * sc;
}

// ---------------- tf32 mma.sync GEMM, W-resident + reg-prefetch pipeline ----------------
// C[i,j] = sum_k A[i,k]*W[j,k] + bias[j]
// MODE 0: A = g_agg -> C = g_h1, fused BN column stats.  MODE 1: A = BNReLU(g_h1) -> C = out.
// Block: 128x128 tile, 256 thr, 8 warps (2m x 4n), warp tile 64x32.
__device__ __forceinline__ void mma_tf32(float* c, const uint32_t* a, const uint32_t* b) {
    asm volatile("mma.sync.aligned.m16n8k8.row.col.f32.tf32.tf32.f32 "
                 "{%0,%1,%2,%3}, {%4,%5,%6,%7}, {%8,%9}, {%0,%1,%2,%3};"
                 : "+f"(c[0]), "+f"(c[1]), "+f"(c[2]), "+f"(c[3])
                 : "r"(a[0]), "r"(a[1]), "r"(a[2]), "r"(a[3]), "r"(b[0]), "r"(b[1]));
}

template <int MODE>
__global__ void __launch_bounds__(256, 2) k_gemm_mma(const float* __restrict__ Wm,
                                                     const float* __restrict__ bias,
                                                     float* __restrict__ outp, int nrows) {
    __shared__ float sW[128][132];      // full W, tf32-rounded; stride 132 (mod 32 = 4) conflict-free
    __shared__ float sA[2][128][36];    // double-buffered A chunk (32 k)

    const float* __restrict__ A = (MODE == 0) ? g_agg : g_h1;
    float* __restrict__ Cp      = (MODE == 0) ? g_h1  : outp;

    int tid  = threadIdx.x;
    int wid  = tid >> 5, lane = tid & 31;
    int g    = lane >> 2, t4 = lane & 3;
    int wm   = (wid >> 2) * 64;
    int wn   = (wid & 3) * 32;
    int rowbase = blockIdx.x * 128;

    // ---- load full W into smem (tf32-rounded) ----
#pragma unroll
    for (int it = 0; it < 16; ++it) {
        int i  = tid + it * 256;        // 0..4095 float4 slots
        int r  = i >> 5;                // 0..127
        int c4 = i & 31;                // float4 within 128-float row
        float4 v = ((const float4*)Wm)[(size_t)r * D4 + c4];
        float* p = &sW[r][c4 * 4];
        p[0] = __uint_as_float(f2tf32(v.x));
        p[1] = __uint_as_float(f2tf32(v.y));
        p[2] = __uint_as_float(f2tf32(v.z));
        p[3] = __uint_as_float(f2tf32(v.w));
    }

    float acc[4][4][4];
#pragma unroll
    for (int mi = 0; mi < 4; mi++)
#pragma unroll
        for (int nj = 0; nj < 4; nj++)
#pragma unroll
            for (int q = 0; q < 4; q++) acc[mi][nj][q] = 0.f;

    // ---- prefetch A chunk 0 into registers ----
    float4 pf[4];
    {
        int r  = tid >> 3;              // thread's fixed row slot pattern
        int c4 = tid & 7;
#pragma unroll
        for (int it = 0; it < 4; ++it) {
            int rr = r + it * 32;
            int grow = rowbase + rr;
            pf[it] = make_float4(0.f, 0.f, 0.f, 0.f);
            if (grow < nrows) pf[it] = ((const float4*)A)[(size_t)grow * D4 + c4];
        }
    }
    __syncthreads();   // W visible; (also joins warps before chunk stores)

    int rS  = tid >> 3;
    int c4S = tid & 7;

    for (int kc = 0; kc < 4; ++kc) {
        int buf = kc & 1;
        // ---- store prefetched chunk to smem (with MODE-1 BN transform), tf32-rounded ----
#pragma unroll
        for (int it = 0; it < 4; ++it) {
            float4 v = pf[it];
            if (MODE == 1) {
                int k0 = kc * 32 + c4S * 4;
                float4 sc = *(const float4*)&g_scale[k0];
                float4 sh = *(const float4*)&g_shift[k0];
                v.x = fmaxf(fmaf(v.x, sc.x, sh.x), 0.f);
                v.y = fmaxf(fmaf(v.y, sc.y, sh.y), 0.f);
                v.z = fmaxf(fmaf(v.z, sc.z, sh.z), 0.f);
                v.w = fmaxf(fmaf(v.w, sc.w, sh.w), 0.f);
            }
            float* p = &sA[buf][rS + it * 32][c4S * 4];
            p[0] = __uint_as_float(f2tf32(v.x));
            p[1] = __uint_as_float(f2tf32(v.y));
            p[2] = __uint_as_float(f2tf32(v.z));
            p[3] = __uint_as_float(f2tf32(v.w));
        }
        __syncthreads();

        // ---- prefetch next chunk (overlaps with MMA below) ----
        if (kc < 3) {
#pragma unroll
            for (int it = 0; it < 4; ++it) {
                int grow = rowbase + rS + it * 32;
                pf[it] = make_float4(0.f, 0.f, 0.f, 0.f);
                if (grow < nrows) pf[it] = ((const float4*)A)[(size_t)grow * D4 + (kc + 1) * 8 + c4S];
            }
        }

        // ---- MMAs over this chunk ----
#pragma unroll
        for (int ks = 0; ks < 4; ++ks) {
            int ka = ks * 8;                 // k within sA chunk
            int kw = kc * 32 + ka;           // k within sW
            uint32_t af[4][4];
#pragma unroll
            for (int mi = 0; mi < 4; mi++) {
                int r = wm + mi * 16 + g;
                af[mi][0] = __float_as_uint(sA[buf][r    ][ka + t4    ]);
                af[mi][1] = __float_as_uint(sA[buf][r + 8][ka + t4    ]);
                af[mi][2] = __float_as_uint(sA[buf][r    ][ka + t4 + 4]);
                af[mi][3] = __float_as_uint(sA[buf][r + 8][ka + t4 + 4]);
            }
            uint32_t bf[4][2];
#pragma unroll
            for (int nj = 0; nj < 4; nj++) {
                int c = wn + nj * 8 + g;
                bf[nj][0] = __float_as_uint(sW[c][kw + t4    ]);
                bf[nj][1] = __float_as_uint(sW[c][kw + t4 + 4]);
            }
#pragma unroll
            for (int mi = 0; mi < 4; mi++)
#pragma unroll
                for (int nj = 0; nj < 4; nj++)
                    mma_tf32(acc[mi][nj], af[mi], bf[nj]);
        }
        // no trailing sync needed: next store targets the other buffer, and the
        // per-iteration sync orders mma(k-1) before any store(k+1).
    }

    // ---- epilogue: bias add, store, (MODE 0) fused BN column stats ----
    float bj0[4], bj1[4];
#pragma unroll
    for (int nj = 0; nj < 4; nj++) {
        int c = wn + nj * 8 + 2 * t4;
        bj0[nj] = bias[c];
        bj1[nj] = bias[c + 1];
    }

    float s0[4], s1[4], q0[4], q1[4];
#pragma unroll
    for (int nj = 0; nj < 4; nj++) { s0[nj] = s1[nj] = q0[nj] = q1[nj] = 0.f; }

#pragma unroll
    for (int mi = 0; mi < 4; mi++) {
        int r0 = rowbase + wm + mi * 16 + g;
        int r1 = r0 + 8;
#pragma unroll
        for (int nj = 0; nj < 4; nj++) {
            int c = wn + nj * 8 + 2 * t4;
            float v00 = acc[mi][nj][0] + bj0[nj];
            float v01 = acc[mi][nj][1] + bj1[nj];
            float v10 = acc[mi][nj][2] + bj0[nj];
            float v11 = acc[mi][nj][3] + bj1[nj];
            if (r0 < nrows) {
                *(float2*)&Cp[(size_t)r0 * D + c] = make_float2(v00, v01);
                if (MODE == 0) {
                    s0[nj] += v00; s1[nj] += v01;
                    q0[nj] = fmaf(v00, v00, q0[nj]); q1[nj] = fmaf(v01, v01, q1[nj]);
                }
            }
            if (r1 < nrows) {
                *(float2*)&Cp[(size_t)r1 * D + c] = make_float2(v10, v11);
                if (MODE == 0) {
                    s0[nj] += v10; s1[nj] += v11;
                    q0[nj] = fmaf(v10, v10, q0[nj]); q1[nj] = fmaf(v11, v11, q1[nj]);
                }
            }
        }
    }

    if (MODE == 0) {
#pragma unroll
        for (int nj = 0; nj < 4; nj++) {
#pragma unroll
            for (int m = 4; m <= 16; m <<= 1) {
                s0[nj] += __shfl_xor_sync(0xFFFFFFFFu, s0[nj], m);
                s1[nj] += __shfl_xor_sync(0xFFFFFFFFu, s1[nj], m);
                q0[nj] += __shfl_xor_sync(0xFFFFFFFFu, q0[nj], m);
                q1[nj] += __shfl_xor_sync(0xFFFFFFFFu, q1[nj], m);
            }
        }
        if (lane < 4) {
#pragma unroll
            for (int nj = 0; nj < 4; nj++) {
                int c = wn + nj * 8 + 2 * t4;
                atomicAdd(&g_sum[c],     s0[nj]);
                atomicAdd(&g_sum[c + 1], s1[nj]);
                atomicAdd(&g_sq [c],     q0[nj]);
                atomicAdd(&g_sq [c + 1], q1[nj]);
            }
        }
    }
}

// ---------------- launch ----------------
extern "C" void kernel_launch(void* const* d_in, const int* in_sizes, int n_in,
                              void* d_out, int out_size) {
    const float* x     = (const float*)d_in[0];
    const int*   src   = (const int*)d_in[1];
    const int*   dst   = (const int*)d_in[2];
    const float* W1    = (const float*)d_in[3];
    const float* b1    = (const float*)d_in[4];
    const float* gamma = (const float*)d_in[5];
    const float* beta  = (const float*)d_in[6];
    const float* W2    = (const float*)d_in[7];
    const float* b2    = (const float*)d_in[8];
    const float* eps   = (const float*)d_in[9];
    float* out = (float*)d_out;

    int N = in_sizes[0] / D;     // 40000
    int E = in_sizes[1];         // 640000
    int n4 = N * D4;

    k_init_agg<<<(n4 + 255) / 256, 256>>>(x, eps, n4);
    k_scatter<<<2048, 256>>>(x, src, dst, E, N);

    int gb = (N + 127) / 128;
    k_gemm_mma<0><<<gb, 256>>>(W1, b1, nullptr, N);   // + fused BN stats
    k_bnfinal<<<1, 128>>>(gamma, beta, N);
    k_gemm_mma<1><<<gb, 256>>>(W2, b2, out, N);
}